// round 17
// baseline (speedup 1.0000x reference)
#include <cuda_runtime.h>
#include <cuda_fp16.h>
#include <cstdint>

// ============================================================================
// Multihead_Attention (no-softmax => fully linear) on sm_100 (generic PTX).
// R17: R16 (proven) +
//   1. single fused split launch (6 tensors)
//   2. compute_mT 256-t slices (half the partial traffic)
//   3. EXPERIMENT: gemm_out with fp16-accum HMMA, fp32 promote every k64
//      (tests the 2x fp16-accum rate hypothesis for the legacy mma pipe)
// Error model: sqrt(7.19^2 + 3^2) ~ 7.8e-4 (threshold 1e-3).
// ============================================================================

#define MROWS 4096
#define DMODEL 1024

__device__ float g_Mpart[8 * 32 * 64 * 64];      // M^T partials (fp32)
__device__ __half g_MTh[32 * 64 * 64];           // M^T fp16

__device__ __half g_xh[MROWS * DMODEL];
__device__ __half g_yh[MROWS * DMODEL];
__device__ __half g_Qh[MROWS * DMODEL];
__device__ __half g_Kh[MROWS * DMODEL];
__device__ __half g_Vh[MROWS * DMODEL];
__device__ __half g_Oh[MROWS * DMODEL];
__device__ __half g_qwh[DMODEL * DMODEL];
__device__ __half g_kwh[DMODEL * DMODEL];
__device__ __half g_vwh[DMODEL * DMODEL];
__device__ __half g_owh[DMODEL * DMODEL];

// ---------------- generic PTX helpers ---------------------------------------
__device__ __forceinline__ uint32_t smem_u32(const void* p) {
    uint32_t a;
    asm("{ .reg .u64 t; cvta.to.shared.u64 t, %1; cvt.u32.u64 %0, t; }"
        : "=r"(a) : "l"(p));
    return a;
}
__device__ __forceinline__ void cp16(uint32_t dst, const void* src) {
    asm volatile("cp.async.cg.shared.global [%0], [%1], 16;"
                 :: "r"(dst), "l"(src) : "memory");
}
__device__ __forceinline__ void ldsm4(uint32_t (&r)[4], uint32_t addr) {
    asm volatile("ldmatrix.sync.aligned.m8n8.x4.shared.b16 {%0,%1,%2,%3}, [%4];"
                 : "=r"(r[0]), "=r"(r[1]), "=r"(r[2]), "=r"(r[3]) : "r"(addr));
}
__device__ __forceinline__ void mma_f16(float (&d)[4], const uint32_t (&a)[4],
                                        uint32_t b0, uint32_t b1) {
    asm volatile(
        "mma.sync.aligned.m16n8k16.row.col.f32.f16.f16.f32 "
        "{%0,%1,%2,%3}, {%4,%5,%6,%7}, {%8,%9}, {%0,%1,%2,%3};"
        : "+f"(d[0]), "+f"(d[1]), "+f"(d[2]), "+f"(d[3])
        : "r"(a[0]), "r"(a[1]), "r"(a[2]), "r"(a[3]), "r"(b0), "r"(b1));
}
// fp16-accumulator variant (2 output regs = 4 halves)
__device__ __forceinline__ void mma_f16acc(uint32_t (&d)[2], const uint32_t (&a)[4],
                                           uint32_t b0, uint32_t b1) {
    asm volatile(
        "mma.sync.aligned.m16n8k16.row.col.f16.f16.f16.f16 "
        "{%0,%1}, {%2,%3,%4,%5}, {%6,%7}, {%0,%1};"
        : "+r"(d[0]), "+r"(d[1])
        : "r"(a[0]), "r"(a[1]), "r"(a[2]), "r"(a[3]), "r"(b0), "r"(b1));
}

// pack 4 fp32 -> fp16x4 (uint2)
__device__ __forceinline__ uint2 pack4_f16(float4 v) {
    __half2 p0 = __floats2half2_rn(v.x, v.y);
    __half2 p1 = __floats2half2_rn(v.z, v.w);
    uint2 hv;
    hv.x = *reinterpret_cast<uint32_t*>(&p0);
    hv.y = *reinterpret_cast<uint32_t*>(&p1);
    return hv;
}

// ============================================================================
// fused split: all 6 fp32->fp16 conversions in one launch.
// grid (4096, 6). acts (y=0,1) use all 4096 blocks; weights (y=2..5) use 1024.
// ============================================================================
__global__ __launch_bounds__(256)
void split_all(const float* __restrict__ x, const float* __restrict__ y,
               const float* __restrict__ qw, const float* __restrict__ kw,
               const float* __restrict__ vw, const float* __restrict__ ow,
               __half* __restrict__ xh, __half* __restrict__ yh,
               __half* __restrict__ qwh, __half* __restrict__ kwh,
               __half* __restrict__ vwh, __half* __restrict__ owh) {
    const int t = blockIdx.y;
    if (t >= 2 && blockIdx.x >= 1024) return;
    const float* src = (t == 0) ? x : (t == 1) ? y : (t == 2) ? qw
                       : (t == 3) ? kw : (t == 4) ? vw : ow;
    __half* dst = (t == 0) ? xh : (t == 1) ? yh : (t == 2) ? qwh
                  : (t == 3) ? kwh : (t == 4) ? vwh : owh;
    int i = blockIdx.x * 256 + threadIdx.x;
    float4 v = reinterpret_cast<const float4*>(src)[i];
    reinterpret_cast<uint2*>(dst)[i] = pack4_f16(v);
}

// ============================================================================
// pure fp16 GEMM core (R14-proven): C = A @ W^T + bias (fp16 out).
// CTA tile 128x256, BK=64, 3-stage cp.async, 8 warps.
// ============================================================================
#define FQ_AS 18432
#define FQ_W_BASE (3 * FQ_AS)
#define FQ_BS 36864
#define FQ_TOTAL (FQ_W_BASE + 3 * FQ_BS)  // 165888

__global__ __launch_bounds__(256, 1)
void gemm_qkv_f16(const __half* __restrict__ xh, const __half* __restrict__ yh,
                  const __half* __restrict__ qwh, const __half* __restrict__ kwh,
                  const __half* __restrict__ vwh,
                  const float* __restrict__ q_b, const float* __restrict__ k_b,
                  const float* __restrict__ v_b,
                  __half* __restrict__ Q, __half* __restrict__ K,
                  __half* __restrict__ V) {
    extern __shared__ __align__(128) char smem[];
    __shared__ float biasS[256];
    const int z = blockIdx.z;
    const __half* Ah = (z == 2) ? yh : xh;
    const __half* Wh = (z == 0) ? qwh : (z == 1) ? kwh : vwh;
    const float* bias = (z == 0) ? q_b : (z == 1) ? k_b : v_b;
    __half* C = (z == 0) ? Q : (z == 1) ? K : V;
    const int m0 = blockIdx.y << 7;
    const int n0 = blockIdx.x << 8;

    const uint32_t sbase = smem_u32(smem);
    const int tid = threadIdx.x;
    const int lane = tid & 31;
    const int wid = tid >> 5;

    biasS[tid] = bias[n0 + tid];

    auto load_stage = [&](int kt, int s) {
        const int kcol = kt << 6;
        const uint32_t sa = sbase + s * FQ_AS;
        const uint32_t sb = sbase + FQ_W_BASE + s * FQ_BS;
#pragma unroll
        for (int u = 0; u < 4; u++) {
            int idx = tid + (u << 8);
            int r = idx >> 3, c = idx & 7;
            cp16(sa + r * 144 + c * 16, Ah + (m0 + r) * DMODEL + kcol + c * 8);
        }
#pragma unroll
        for (int u = 0; u < 8; u++) {
            int idx = tid + (u << 8);
            int r = idx >> 3, c = idx & 7;
            cp16(sb + r * 144 + c * 16, Wh + (n0 + r) * DMODEL + kcol + c * 8);
        }
    };

    load_stage(0, 0);
    asm volatile("cp.async.commit_group;" ::: "memory");
    load_stage(1, 1);
    asm volatile("cp.async.commit_group;" ::: "memory");

    float d[4][8][4];
#pragma unroll
    for (int mf = 0; mf < 4; mf++)
#pragma unroll
        for (int nf = 0; nf < 8; nf++)
#pragma unroll
            for (int q = 0; q < 4; q++) d[mf][nf][q] = 0.f;

    const int warpM = (wid >> 2) << 6;
    const int warpN = (wid & 3) << 6;
    const uint32_t aLane = (warpM + (lane & 15)) * 144 + (lane >> 4) * 16;
    const uint32_t bLane = (warpN + ((lane >> 4) & 1) * 8 + (lane & 7)) * 144 +
                           ((lane >> 3) & 1) * 16;

    for (int it = 0; it < 16; ++it) {
        const int buf = it % 3;
        if (it < 15)
            asm volatile("cp.async.wait_group 1;" ::: "memory");
        else
            asm volatile("cp.async.wait_group 0;" ::: "memory");
        __syncthreads();
        if (it + 2 < 16) {
            load_stage(it + 2, (it + 2) % 3);
            asm volatile("cp.async.commit_group;" ::: "memory");
        }
        const uint32_t sa = sbase + buf * FQ_AS + aLane;
        const uint32_t sb = sbase + FQ_W_BASE + buf * FQ_BS + bLane;

#pragma unroll
        for (int kc = 0; kc < 4; kc++) {
            const uint32_t ko = kc * 32;
            uint32_t a[4][4], bb[4][4];
#pragma unroll
            for (int mf = 0; mf < 4; mf++) ldsm4(a[mf], sa + mf * 2304 + ko);
#pragma unroll
            for (int nf2 = 0; nf2 < 4; nf2++) ldsm4(bb[nf2], sb + nf2 * 2304 + ko);
#pragma unroll
            for (int mf = 0; mf < 4; mf++)
#pragma unroll
                for (int nf = 0; nf < 8; nf++)
                    mma_f16(d[mf][nf], a[mf], bb[nf >> 1][(nf & 1) * 2],
                            bb[nf >> 1][(nf & 1) * 2 + 1]);
        }
    }

    const int rsub = lane >> 2;
    const int csub = (lane & 3) * 2;
#pragma unroll
    for (int mf = 0; mf < 4; mf++) {
#pragma unroll
        for (int nf = 0; nf < 8; nf++) {
            const int row = m0 + warpM + mf * 16 + rsub;
            const int colL = warpN + nf * 8 + csub;
            const float b0 = biasS[colL], b1 = biasS[colL + 1];
            __half2 v0 = __floats2half2_rn(d[mf][nf][0] + b0, d[mf][nf][1] + b1);
            __half2 v1 = __floats2half2_rn(d[mf][nf][2] + b0, d[mf][nf][3] + b1);
            *reinterpret_cast<__half2*>(&C[(size_t)row * DMODEL + n0 + colL]) = v0;
            *reinterpret_cast<__half2*>(&C[(size_t)(row + 8) * DMODEL + n0 + colL]) = v1;
        }
    }
}

// ============================================================================
// gemm_out with fp16-accumulator HMMA (EXPERIMENT): fp32 promote every k64.
// Same tile/addressing as the proven core; mainloop restructured in two
// mf-halves (h regs = 32) so master fp32 accum + fp16 temps fit in registers.
// ============================================================================
__global__ __launch_bounds__(256, 1)
void gemm_out_f16acc(const __half* __restrict__ Ah, const __half* __restrict__ Wh,
                     const float* __restrict__ bias, float* __restrict__ out) {
    extern __shared__ __align__(128) char smem[];
    __shared__ float biasS[256];
    const int m0 = blockIdx.y << 7;
    const int n0 = blockIdx.x << 8;

    const uint32_t sbase = smem_u32(smem);
    const int tid = threadIdx.x;
    const int lane = tid & 31;
    const int wid = tid >> 5;

    biasS[tid] = bias[n0 + tid];

    auto load_stage = [&](int kt, int s) {
        const int kcol = kt << 6;
        const uint32_t sa = sbase + s * FQ_AS;
        const uint32_t sb = sbase + FQ_W_BASE + s * FQ_BS;
#pragma unroll
        for (int u = 0; u < 4; u++) {
            int idx = tid + (u << 8);
            int r = idx >> 3, c = idx & 7;
            cp16(sa + r * 144 + c * 16, Ah + (m0 + r) * DMODEL + kcol + c * 8);
        }
#pragma unroll
        for (int u = 0; u < 8; u++) {
            int idx = tid + (u << 8);
            int r = idx >> 3, c = idx & 7;
            cp16(sb + r * 144 + c * 16, Wh + (n0 + r) * DMODEL + kcol + c * 8);
        }
    };

    load_stage(0, 0);
    asm volatile("cp.async.commit_group;" ::: "memory");
    load_stage(1, 1);
    asm volatile("cp.async.commit_group;" ::: "memory");

    float d[4][8][4];
#pragma unroll
    for (int mf = 0; mf < 4; mf++)
#pragma unroll
        for (int nf = 0; nf < 8; nf++)
#pragma unroll
            for (int q = 0; q < 4; q++) d[mf][nf][q] = 0.f;

    const int warpM = (wid >> 2) << 6;
    const int warpN = (wid & 3) << 6;
    const uint32_t aLane = (warpM + (lane & 15)) * 144 + (lane >> 4) * 16;
    const uint32_t bLane = (warpN + ((lane >> 4) & 1) * 8 + (lane & 7)) * 144 +
                           ((lane >> 3) & 1) * 16;

    for (int it = 0; it < 16; ++it) {
        const int buf = it % 3;
        if (it < 15)
            asm volatile("cp.async.wait_group 1;" ::: "memory");
        else
            asm volatile("cp.async.wait_group 0;" ::: "memory");
        __syncthreads();
        if (it + 2 < 16) {
            load_stage(it + 2, (it + 2) % 3);
            asm volatile("cp.async.commit_group;" ::: "memory");
        }
        const uint32_t sa = sbase + buf * FQ_AS + aLane;
        const uint32_t sb = sbase + FQ_W_BASE + buf * FQ_BS + bLane;

#pragma unroll
        for (int mh = 0; mh < 2; mh++) {
            uint32_t h[2][8][2];
#pragma unroll
            for (int i = 0; i < 2; i++)
#pragma unroll
                for (int nf = 0; nf < 8; nf++) { h[i][nf][0] = 0u; h[i][nf][1] = 0u; }

#pragma unroll
            for (int kc = 0; kc < 4; kc++) {
                const uint32_t ko = kc * 32;
                uint32_t a[2][4], bb[4][4];
                ldsm4(a[0], sa + (mh * 2 + 0) * 2304 + ko);
                ldsm4(a[1], sa + (mh * 2 + 1) * 2304 + ko);
#pragma unroll
                for (int nf2 = 0; nf2 < 4; nf2++)
                    ldsm4(bb[nf2], sb + nf2 * 2304 + ko);
#pragma unroll
                for (int i = 0; i < 2; i++)
#pragma unroll
                    for (int nf = 0; nf < 8; nf++)
                        mma_f16acc(h[i][nf], a[i], bb[nf >> 1][(nf & 1) * 2],
                                   bb[nf >> 1][(nf & 1) * 2 + 1]);
            }
            // promote fp16 partials to fp32 master
#pragma unroll
            for (int i = 0; i < 2; i++)
#pragma unroll
                for (int nf = 0; nf < 8; nf++) {
                    float2 p0 = __half22float2(*reinterpret_cast<__half2*>(&h[i][nf][0]));
                    float2 p1 = __half22float2(*reinterpret_cast<__half2*>(&h[i][nf][1]));
                    d[mh * 2 + i][nf][0] += p0.x;
                    d[mh * 2 + i][nf][1] += p0.y;
                    d[mh * 2 + i][nf][2] += p1.x;
                    d[mh * 2 + i][nf][3] += p1.y;
                }
        }
    }

    const int rsub = lane >> 2;
    const int csub = (lane & 3) * 2;
#pragma unroll
    for (int mf = 0; mf < 4; mf++) {
#pragma unroll
        for (int nf = 0; nf < 8; nf++) {
            const int row = m0 + warpM + mf * 16 + rsub;
            const int colL = warpN + nf * 8 + csub;
            const float b0 = biasS[colL], b1 = biasS[colL + 1];
            float2 v0 = make_float2(d[mf][nf][0] + b0, d[mf][nf][1] + b1);
            float2 v1 = make_float2(d[mf][nf][2] + b0, d[mf][nf][3] + b1);
            *reinterpret_cast<float2*>(&out[(size_t)row * DMODEL + n0 + colL]) = v0;
            *reinterpret_cast<float2*>(&out[(size_t)(row + 8) * DMODEL + n0 + colL]) = v1;
        }
    }
}

// ============================================================================
// compute_mT: MT_g[d',d] partial over a 256-t slice (two 128-t smem passes).
// grid (8, 32). Proven transpose-fill + non-trans ldsm addressing (R16).
// ============================================================================
__global__ __launch_bounds__(256)
void compute_mT(const __half* __restrict__ Kh, const __half* __restrict__ Vh,
                float* __restrict__ Mpart) {
    __shared__ __align__(16) __half KsT[64 * 136];
    __shared__ __align__(16) __half VsT[64 * 136];
    const int s = blockIdx.x;
    const int g = blockIdx.y;
    const int tid = threadIdx.x;
    const int lane = tid & 31;
    const int wid = tid >> 5;

    const uint32_t sK = smem_u32(KsT);
    const uint32_t sV = smem_u32(VsT);
    const int wm = wid >> 1;
    const int wn = wid & 1;
    const uint32_t aLane = sV + (wm * 16 + (lane & 15)) * 272 + (lane >> 4) * 16;
    const uint32_t bLane = sK + (wn * 32 + ((lane >> 4) & 1) * 8 + (lane & 7)) * 272 +
                           ((lane >> 3) & 1) * 16;

    float d[4][4];
#pragma unroll
    for (int nf = 0; nf < 4; nf++)
#pragma unroll
        for (int q = 0; q < 4; q++) d[nf][q] = 0.f;

    for (int p = 0; p < 2; p++) {
        if (p) __syncthreads();   // all warps done reading before refill
        const int gsrc = g * 131072 + s * 16384 + p * 8192;
#pragma unroll
        for (int u = 0; u < 4; u++) {
            int idx = tid + (u << 8);
            int t = idx & 127;
            int d8 = (idx >> 7) << 3;
            float4 kv = *reinterpret_cast<const float4*>(&Kh[gsrc + t * 64 + d8]);
            float4 vv = *reinterpret_cast<const float4*>(&Vh[gsrc + t * 64 + d8]);
            const __half* kp = reinterpret_cast<const __half*>(&kv);
            const __half* vp = reinterpret_cast<const __half*>(&vv);
#pragma unroll
            for (int e = 0; e < 8; e++) {
                KsT[(d8 + e) * 136 + t] = kp[e];
                VsT[(d8 + e) * 136 + t] = vp[e];
            }
        }
        __syncthreads();

#pragma unroll
        for (int kc = 0; kc < 8; kc++) {
            const uint32_t ko = kc * 32;
            uint32_t a[4], bb[2][4];
            ldsm4(a, aLane + ko);
            ldsm4(bb[0], bLane + ko);
            ldsm4(bb[1], bLane + ko + 16 * 272);
#pragma unroll
            for (int nf = 0; nf < 4; nf++)
                mma_f16(d[nf], a, bb[nf >> 1][(nf & 1) * 2],
                        bb[nf >> 1][(nf & 1) * 2 + 1]);
        }
    }

    const int rsub = lane >> 2;
    const int csub = (lane & 3) * 2;
    float* dst = Mpart + (size_t)(s * 32 + g) * 4096;
#pragma unroll
    for (int nf = 0; nf < 4; nf++) {
        int dp = wm * 16 + rsub;
        int dc = wn * 32 + nf * 8 + csub;
        *reinterpret_cast<float2*>(&dst[dp * 64 + dc]) =
            make_float2(d[nf][0], d[nf][1]);
        *reinterpret_cast<float2*>(&dst[(dp + 8) * 64 + dc]) =
            make_float2(d[nf][2], d[nf][3]);
    }
}

// reduce 8 partials, scale 1/32, emit fp16 M^T
__global__ __launch_bounds__(256)
void reduce_mT(const float* __restrict__ Mpart, __half* __restrict__ MTh) {
    int i = blockIdx.x * 256 + threadIdx.x;  // 131072
    float acc = 0.f;
#pragma unroll
    for (int s = 0; s < 8; s++) acc += Mpart[s * 131072 + i];
    MTh[i] = __float2half_rn(acc * 0.03125f);
}

// ============================================================================
// apply_mma: O[r, j*64+d'] = sum_d Q[r, j*64+d] * M[d][d']   (HMMA, R16-proven)
// ============================================================================
__global__ __launch_bounds__(256)
void apply_mma(const __half* __restrict__ Qh, const __half* __restrict__ MTh,
               __half* __restrict__ Oh) {
    __shared__ __align__(16) __half Qs[128 * 72];
    __shared__ __align__(16) __half Ms[64 * 72];
    const int j = blockIdx.x;
    const int g = blockIdx.y;
    const int tid = threadIdx.x;
    const int lane = tid & 31;
    const int wid = tid >> 5;

    const uint32_t sQ = smem_u32(Qs);
    const uint32_t sM = smem_u32(Ms);

#pragma unroll
    for (int u = 0; u < 4; u++) {
        int idx = tid + (u << 8);
        int r = idx >> 3, c = idx & 7;
        *reinterpret_cast<float4*>(&Qs[r * 72 + c * 8]) =
            *reinterpret_cast<const float4*>(
                &Qh[(size_t)(g * 128 + r) * DMODEL + (j << 6) + c * 8]);
    }
#pragma unroll
    for (int u = 0; u < 2; u++) {
        int idx = tid + (u << 8);
        int r = idx >> 3, c = idx & 7;
        *reinterpret_cast<float4*>(&Ms[r * 72 + c * 8]) =
            *reinterpret_cast<const float4*>(&MTh[g * 4096 + r * 64 + c * 8]);
    }
    __syncthreads();

    const int wm = wid;
    const uint32_t aLane = sQ + (wm * 16 + (lane & 15)) * 144 + (lane >> 4) * 16;
    const uint32_t bLane = sM + (((lane >> 4) & 1) * 8 + (lane & 7)) * 144 +
                           ((lane >> 3) & 1) * 16;

    float d[8][4];
#pragma unroll
    for (int nf = 0; nf < 8; nf++)
#pragma unroll
        for (int q = 0; q < 4; q++) d[nf][q] = 0.f;

#pragma unroll
    for (int kc = 0; kc < 4; kc++) {
        const uint32_t ko = kc * 32;
        uint32_t a[4], bb[4][4];
        ldsm4(a, aLane + ko);
#pragma unroll
        for (int nf2 = 0; nf2 < 4; nf2++) ldsm4(bb[nf2], bLane + nf2 * 2304 + ko);
#pragma unroll
        for (int nf = 0; nf < 8; nf++)
            mma_f16(d[nf], a, bb[nf >> 1][(nf & 1) * 2],
                    bb[nf >> 1][(nf & 1) * 2 + 1]);
    }

    const int rsub = lane >> 2;
    const int csub = (lane & 3) * 2;
#pragma unroll
    for (int nf = 0; nf < 8; nf++) {
        int row = g * 128 + wm * 16 + rsub;
        int col = (j << 6) + nf * 8 + csub;
        __half2 v0 = __floats2half2_rn(d[nf][0], d[nf][1]);
        __half2 v1 = __floats2half2_rn(d[nf][2], d[nf][3]);
        *reinterpret_cast<__half2*>(&Oh[(size_t)row * DMODEL + col]) = v0;
        *reinterpret_cast<__half2*>(&Oh[(size_t)(row + 8) * DMODEL + col]) = v1;
    }
}

// ============================================================================
extern "C" void kernel_launch(void* const* d_in, const int* in_sizes, int n_in,
                              void* d_out, int out_size) {
    const float* x   = (const float*)d_in[0];
    const float* y   = (const float*)d_in[1];
    const float* q_w = (const float*)d_in[2];
    const float* q_b = (const float*)d_in[3];
    const float* k_w = (const float*)d_in[4];
    const float* k_b = (const float*)d_in[5];
    const float* v_w = (const float*)d_in[6];
    const float* v_b = (const float*)d_in[7];
    const float* o_w = (const float*)d_in[8];
    const float* o_b = (const float*)d_in[9];
    float* out = (float*)d_out;

    float* Mpp;
    __half *MTh, *xh, *yh, *Qh, *Kh, *Vh, *Oh, *qwh, *kwh, *vwh, *owh;
    cudaGetSymbolAddress((void**)&Mpp, g_Mpart);
    cudaGetSymbolAddress((void**)&MTh, g_MTh);
    cudaGetSymbolAddress((void**)&xh, g_xh);
    cudaGetSymbolAddress((void**)&yh, g_yh);
    cudaGetSymbolAddress((void**)&Qh, g_Qh);
    cudaGetSymbolAddress((void**)&Kh, g_Kh);
    cudaGetSymbolAddress((void**)&Vh, g_Vh);
    cudaGetSymbolAddress((void**)&Oh, g_Oh);
    cudaGetSymbolAddress((void**)&qwh, g_qwh);
    cudaGetSymbolAddress((void**)&kwh, g_kwh);
    cudaGetSymbolAddress((void**)&vwh, g_vwh);
    cudaGetSymbolAddress((void**)&owh, g_owh);

    cudaFuncSetAttribute(gemm_qkv_f16, cudaFuncAttributeMaxDynamicSharedMemorySize,
                         FQ_TOTAL);
    cudaFuncSetAttribute(gemm_out_f16acc, cudaFuncAttributeMaxDynamicSharedMemorySize,
                         FQ_TOTAL);

    split_all<<<dim3(4096, 6), 256>>>(x, y, q_w, k_w, v_w, o_w,
                                      xh, yh, qwh, kwh, vwh, owh);

    gemm_qkv_f16<<<dim3(DMODEL / 256, MROWS / 128, 3), 256, FQ_TOTAL>>>(
        xh, yh, qwh, kwh, vwh, q_b, k_b, v_b, Qh, Kh, Vh);

    compute_mT<<<dim3(8, 32), 256>>>(Kh, Vh, Mpp);
    reduce_mT<<<512, 256>>>(Mpp, MTh);
    apply_mma<<<dim3(16, 32), 256>>>(Qh, MTh, Oh);

    gemm_out_f16acc<<<dim3(DMODEL / 256, MROWS / 128), 256, FQ_TOTAL>>>(
        Oh, owh, o_b, out);
}